// round 5
// baseline (speedup 1.0000x reference)
#include <cuda_runtime.h>

// GCBFSafetyLayer: reference QP projection uses A = L_g_h = zeros, so every
// per-constraint update is gated off by (nrm > 1e-6) == false;
// safe_action == raw_action exactly (bit-identical). The optimal "kernel" is
// whatever mechanism moves d_in[3] -> d_out (32 KB D2D) with the least fixed
// overhead.
//
// Measured kernel-node variants (all noise-equivalent, ~3.6-3.9us kernel,
// ~4.6us total): grid 8x256 / 16x128, branchy/branchless. grid=1 regressed.
// This round tests the only remaining distinct mechanism: a graph MEMCPY
// node via cudaMemcpyAsync D2D (allowed by harness rules, graph-capturable).
// If the driver routes it to an SM copy -> expect ~4.2-4.5us; if to the copy
// engine -> regression, and we revert to the R4 kernel next round.

__global__ void __launch_bounds__(128, 1)
copy_exact_kernel(const float4* __restrict__ src, float4* __restrict__ dst) {
    int i = blockIdx.x * blockDim.x + threadIdx.x;
    dst[i] = src[i];
}

__global__ void copy_generic_kernel(const float* __restrict__ src,
                                    float* __restrict__ dst, int n) {
    int i = blockIdx.x * blockDim.x + threadIdx.x;
    if (i < n) dst[i] = src[i];
}

extern "C" void kernel_launch(void* const* d_in, const int* in_sizes, int n_in,
                              void* d_out, int out_size) {
    const float* raw_action = (const float*)d_in[3];
    float* out = (float*)d_out;

    if (out_size == 8192) {
        // 32 KB device-to-device memcpy node on the capturing (default) stream.
        cudaMemcpyAsync(out, raw_action, (size_t)out_size * sizeof(float),
                        cudaMemcpyDeviceToDevice, 0);
    } else if ((out_size & 511) == 0) {
        int blocks = out_size / 512;
        copy_exact_kernel<<<blocks, 128>>>((const float4*)raw_action,
                                           (float4*)out);
    } else {
        int threads = 256;
        int blocks = (out_size + threads - 1) / threads;
        copy_generic_kernel<<<blocks, threads>>>(raw_action, out, out_size);
    }
}